// round 15
// baseline (speedup 1.0000x reference)
#include <cuda_runtime.h>
#include <cuda_fp16.h>
#include <cuda_bf16.h>
#include <math.h>
#include <stdint.h>

// ---------------- problem constants ----------------
#define BB   64          // batch
#define NN   256         // sequence length (K in reference)
#define CC   512         // input channels
#define OO   1024        // qkv channels (2*OUT_PLANES)
#define GG   8           // groups
#define HC   32          // half group planes (q/k channels per group)
#define VC   64          // v channels per group
#define EPSV 1e-5f
#define F_QR 0.1f
#define F_KR 0.1f
#define F_SVE 0.1f
#define F_SV  1.0f

// ---------------- scratch (static device allocations) ----------------
__device__ float d_qkv[(size_t)BB * OO * NN];                 // 64 MB
__device__ float d_bnA[OO];
__device__ float d_bnC[OO];
__device__ __half d_stkh[(size_t)3 * BB * GG * NN * NN];      // 201 MB (qk,qr,kr raw, fp16)
__device__ float d_simstats[48];                              // 24 ch x (sum,sumsq)
__device__ float d_sv [(size_t)BB * GG * VC * NN];            // 33.5 MB
__device__ float d_sve[(size_t)BB * GG * VC * NN];            // 33.5 MB
__device__ float d_outA[OO];
__device__ float d_outC[OO];
__device__ float d_relp[64 * 512];                            // padded v_emb rows (aligned)
// bf16 hi/lo splits for the tensor-core GEMM
__device__ __nv_bfloat16 d_xh[(size_t)BB * NN * CC];          // 16.8 MB
__device__ __nv_bfloat16 d_xl[(size_t)BB * NN * CC];
__device__ __nv_bfloat16 d_wh[(size_t)OO * CC];               // 1 MB
__device__ __nv_bfloat16 d_wl[(size_t)OO * CC];

// ---------------- small helpers ----------------
__device__ __forceinline__ uint32_t smem_u32(const void* p) {
    uint32_t a;
    asm("{ .reg .u64 t; cvta.to.shared.u64 t, %1; cvt.u32.u64 %0, t; }" : "=r"(a) : "l"(p));
    return a;
}
__device__ __forceinline__ void cpa16(uint32_t s, const __nv_bfloat16* g) {
    asm volatile("cp.async.cg.shared.global [%0], [%1], 16;" :: "r"(s), "l"(g));
}
#define CP_COMMIT() asm volatile("cp.async.commit_group;" ::: "memory")
#define CP_WAIT0()  asm volatile("cp.async.wait_group 0;" ::: "memory")

#define LDM4(R0, R1, R2, R3, ADDR)                                              \
    asm volatile("ldmatrix.sync.aligned.m8n8.x4.shared.b16 {%0,%1,%2,%3}, [%4];" \
                 : "=r"(R0), "=r"(R1), "=r"(R2), "=r"(R3) : "r"(ADDR))

#define MMA_BF16(C, A0, A1, A2, A3, B0, B1)                                     \
    asm volatile("mma.sync.aligned.m16n8k16.row.col.f32.bf16.bf16.f32 "         \
                 "{%0,%1,%2,%3}, {%4,%5,%6,%7}, {%8,%9}, {%0,%1,%2,%3};"        \
                 : "+f"((C)[0]), "+f"((C)[1]), "+f"((C)[2]), "+f"((C)[3])       \
                 : "r"(A0), "r"(A1), "r"(A2), "r"(A3), "r"(B0), "r"(B1))

// ---------------- K0: zero sim stats (must run every replay) ----------------
__global__ void k_zero_stats() {
    int t = threadIdx.x;
    if (t < 48) d_simstats[t] = 0.0f;
}

// ---------------- K-prep: fp32 -> bf16 hi/lo split ----------------
__global__ void k_split(const float4* __restrict__ s, uint2* __restrict__ hi,
                        uint2* __restrict__ lo, int n4) {
    int i = blockIdx.x * 256 + threadIdx.x;
    if (i >= n4) return;
    float4 v = s[i];
    float f[4] = {v.x, v.y, v.z, v.w};
    union { __nv_bfloat16 b[4]; uint2 u; } ph, pl;
#pragma unroll
    for (int e = 0; e < 4; e++) {
        __nv_bfloat16 h = __float2bfloat16(f[e]);
        ph.b[e] = h;
        pl.b[e] = __float2bfloat16(f[e] - __bfloat162float(h));
    }
    hi[i] = ph.u;
    lo[i] = pl.u;
}

// ---------------- K-prep: repack v_emb rel rows (64..127) to aligned pitch-512 ----------------
__global__ void k_relprep(const float* __restrict__ rel) {
    int idx = blockIdx.x * 256 + threadIdx.x;   // 64 * 511
    if (idx >= 64 * 511) return;
    int c = idx / 511, t = idx - c * 511;
    d_relp[c * 512 + t] = rel[(size_t)(64 + c) * 511 + t];
}

// ---------------- K1: qkv GEMM via bf16 mma.sync (hi/lo split, cp.async, ldmatrix) ----------
#define SPB    40                       // smem pitch in bf16 (80 B rows: conflict-free)
#define ABYTES (128 * SPB * 2)          // 10240 B per array
#define OWH    0
#define OWL    ABYTES
#define OXH    (2 * ABYTES)
#define OXL    (3 * ABYTES)
#define BUFB   (4 * ABYTES)             // 40960 B per buffer
#define SM_MMA (2 * BUFB)               // 81920 B

__global__ __launch_bounds__(256, 2)
void k_qkv_mma() {
    extern __shared__ char smc[];
    uint32_t sbase = smem_u32(smc);
    int tid = threadIdx.x;
    int n0 = blockIdx.x * 128, o0 = blockIdx.y * 128, b = blockIdx.z;

    int lrow = tid >> 1;
    int seg  = (tid & 1) * 16;
    const __nv_bfloat16* gwh = d_wh + (size_t)(o0 + lrow) * CC + seg;
    const __nv_bfloat16* gwl = d_wl + (size_t)(o0 + lrow) * CC + seg;
    const __nv_bfloat16* gxh = d_xh + ((size_t)b * NN + n0 + lrow) * CC + seg;
    const __nv_bfloat16* gxl = d_xl + ((size_t)b * NN + n0 + lrow) * CC + seg;
    uint32_t sdst = (uint32_t)(lrow * SPB + seg) * 2;

    int warp = tid >> 5, lane = tid & 31;
    int wo = warp >> 2, wn = warp & 3;
    int t8 = lane >> 3, r8 = lane & 7;
    uint32_t aoff = (uint32_t)(((wo * 64 + (t8 & 1) * 8 + r8) * SPB + (t8 >> 1) * 8) * 2);
    uint32_t boff = (uint32_t)(((wn * 32 + (t8 >> 1) * 8 + r8) * SPB + (t8 & 1) * 8) * 2);

    float acc[4][4][4];
#pragma unroll
    for (int mt = 0; mt < 4; mt++)
#pragma unroll
        for (int nt = 0; nt < 4; nt++)
#pragma unroll
            for (int e = 0; e < 4; e++) acc[mt][nt][e] = 0.0f;

    auto stage = [&](int buf, int c0) {
        uint32_t base = sbase + buf * BUFB + sdst;
        cpa16(base + OWH,      gwh + c0);
        cpa16(base + OWH + 16, gwh + c0 + 8);
        cpa16(base + OWL,      gwl + c0);
        cpa16(base + OWL + 16, gwl + c0 + 8);
        cpa16(base + OXH,      gxh + c0);
        cpa16(base + OXH + 16, gxh + c0 + 8);
        cpa16(base + OXL,      gxl + c0);
        cpa16(base + OXL + 16, gxl + c0 + 8);
        CP_COMMIT();
    };

    stage(0, 0);
    for (int kt = 0; kt < 16; kt++) {
        CP_WAIT0();
        __syncthreads();
        if (kt < 15) stage((kt + 1) & 1, (kt + 1) * 32);
        uint32_t cb = sbase + (uint32_t)(kt & 1) * BUFB;
#pragma unroll
        for (int ks = 0; ks < 2; ks++) {
            uint32_t kb = (uint32_t)ks * 32;
            uint32_t bh[2][4], bl[2][4];
#pragma unroll
            for (int ntp = 0; ntp < 2; ntp++) {
                uint32_t ba = cb + boff + (uint32_t)ntp * (16 * SPB * 2) + kb;
                LDM4(bh[ntp][0], bh[ntp][1], bh[ntp][2], bh[ntp][3], ba + OXH);
                LDM4(bl[ntp][0], bl[ntp][1], bl[ntp][2], bl[ntp][3], ba + OXL);
            }
#pragma unroll
            for (int mt = 0; mt < 4; mt++) {
                uint32_t aa = cb + aoff + (uint32_t)mt * (16 * SPB * 2) + kb;
                uint32_t ah[4], al[4];
                LDM4(ah[0], ah[1], ah[2], ah[3], aa + OWH);
                LDM4(al[0], al[1], al[2], al[3], aa + OWL);
#pragma unroll
                for (int nt = 0; nt < 4; nt++) {
                    int ntp = nt >> 1, h = nt & 1;
                    uint32_t b0h = bh[ntp][h * 2], b1h = bh[ntp][h * 2 + 1];
                    uint32_t b0l = bl[ntp][h * 2], b1l = bl[ntp][h * 2 + 1];
                    MMA_BF16(acc[mt][nt], ah[0], ah[1], ah[2], ah[3], b0h, b1h);
                    MMA_BF16(acc[mt][nt], ah[0], ah[1], ah[2], ah[3], b0l, b1l);
                    MMA_BF16(acc[mt][nt], al[0], al[1], al[2], al[3], b0h, b1h);
                }
            }
        }
    }

    int lr = lane >> 2, lc = lane & 3;
    float* outp = d_qkv + ((size_t)b * OO + o0) * NN + n0;
#pragma unroll
    for (int mt = 0; mt < 4; mt++) {
        int orow = wo * 64 + mt * 16 + lr;
#pragma unroll
        for (int nt = 0; nt < 4; nt++) {
            int ncol = wn * 32 + nt * 8 + lc * 2;
            *(float2*)(outp + (size_t)orow * NN + ncol)       = make_float2(acc[mt][nt][0], acc[mt][nt][1]);
            *(float2*)(outp + (size_t)(orow + 8) * NN + ncol) = make_float2(acc[mt][nt][2], acc[mt][nt][3]);
        }
    }
}

// ---------------- block reduce helper ----------------
__device__ __forceinline__ void block_reduce2(float& s, float& ss, float* sh) {
    int tid = threadIdx.x;
    float* shs = sh;
    float* shq = sh + 256;
    shs[tid] = s; shq[tid] = ss;
    __syncthreads();
    for (int step = 128; step > 0; step >>= 1) {
        if (tid < step) { shs[tid] += shs[tid + step]; shq[tid] += shq[tid + step]; }
        __syncthreads();
    }
    s = shs[0]; ss = shq[0];
}

// ---------------- K2: qkv BN -> per-channel affine ----------------
__global__ void k_qkv_stats(const float* __restrict__ gq, const float* __restrict__ bq) {
    __shared__ float sh[512];
    int o = blockIdx.x;
    int tid = threadIdx.x;
    float s = 0.f, ss = 0.f;
    const float* base = d_qkv + (size_t)o * NN + tid;
    for (int b = 0; b < BB; b++) {
        float v = base[(size_t)b * OO * NN];
        s += v; ss += v * v;
    }
    block_reduce2(s, ss, sh);
    if (tid == 0) {
        float m = s / 16384.0f;
        float var = ss / 16384.0f - m * m;
        float a = gq[o] * rsqrtf(var + EPSV);
        d_bnA[o] = a;
        d_bnC[o] = bq[o] - m * a;
    }
}

// ---------------- K3: raw qk/qr/kr + channel stats (diagonal register-tiled) ----------------
#define SR_PQ 68
#define SR_PR 132
__global__ __launch_bounds__(256, 2)
void k_sim_raw(const float* __restrict__ rel) {
    extern __shared__ float sm[];
    float* qs  = sm;
    float* ks  = qs + 32 * SR_PQ;
    float* rqa = ks + 32 * SR_PQ;
    float* rkb = rqa + 32 * SR_PR;
    __shared__ float red[8][6];

    int bx = blockIdx.x;
    int it = bx >> 2, jt = bx & 3;
    int g = blockIdx.y, b = blockIdx.z;
    int i0 = it * 64, j0 = jt * 64;
    int tid = threadIdx.x;

    int offA = 192 + (i0 - j0);
    int offB = 192 + (j0 - i0);
    for (int idx = tid; idx < 32 * 127; idx += 256) {
        int c = idx / 127, t = idx - c * 127;
        rqa[c * SR_PR + t] = rel[(size_t)c * 511 + offA + t];
        rkb[c * SR_PR + t] = rel[(size_t)(32 + c) * 511 + offB + t];
    }
    for (int idx = tid; idx < 2048; idx += 256) {
        int c = idx >> 6, v = idx & 63;
        int oq = g * 128 + c;
        int ok = g * 128 + HC + c;
        qs[c * SR_PQ + v] = d_bnA[oq] * d_qkv[((size_t)b * OO + oq) * NN + i0 + v] + d_bnC[oq];
        ks[c * SR_PQ + v] = d_bnA[ok] * d_qkv[((size_t)b * OO + ok) * NN + j0 + v] + d_bnC[ok];
    }
    __syncthreads();

    int ti = tid >> 4, tj = tid & 15;
    float aqk[4][4], aqr[4][4], akr[4][4];
#pragma unroll
    for (int a = 0; a < 4; a++)
#pragma unroll
        for (int e = 0; e < 4; e++) { aqk[a][e] = 0.f; aqr[a][e] = 0.f; akr[a][e] = 0.f; }

    int baseA = 4 * (ti - tj) + 60;
    int baseB = 4 * (tj - ti) + 60;

#pragma unroll 2
    for (int c = 0; c < 32; c++) {
        float4 q4  = *(const float4*)&qs[c * SR_PQ + ti * 4];
        float4 k4  = *(const float4*)&ks[c * SR_PQ + tj * 4];
        float4 ra0 = *(const float4*)&rqa[c * SR_PR + baseA];
        float4 ra1 = *(const float4*)&rqa[c * SR_PR + baseA + 4];
        float4 rb0 = *(const float4*)&rkb[c * SR_PR + baseB];
        float4 rb1 = *(const float4*)&rkb[c * SR_PR + baseB + 4];
        float qv[4] = {q4.x, q4.y, q4.z, q4.w};
        float kv[4] = {k4.x, k4.y, k4.z, k4.w};
        float ra[8] = {ra0.x, ra0.y, ra0.z, ra0.w, ra1.x, ra1.y, ra1.z, ra1.w};
        float rb[8] = {rb0.x, rb0.y, rb0.z, rb0.w, rb1.x, rb1.y, rb1.z, rb1.w};
#pragma unroll
        for (int a = 0; a < 4; a++)
#pragma unroll
            for (int e = 0; e < 4; e++) {
                aqk[a][e] += qv[a] * kv[e];
                aqr[a][e] += qv[a] * ra[3 + a - e];
                akr[a][e] += kv[e] * rb[3 + e - a];
            }
    }

    float s0 = 0, p0 = 0, s1 = 0, p1 = 0, s2 = 0, p2 = 0;
#pragma unroll
    for (int a = 0; a < 4; a++)
#pragma unroll
        for (int e = 0; e < 4; e++) {
            aqr[a][e] *= F_QR;
            akr[a][e] *= F_KR;
            float v0 = aqk[a][e], v1 = aqr[a][e], v2 = akr[a][e];
            s0 += v0; p0 += v0 * v0;
            s1 += v1; p1 += v1 * v1;
            s2 += v2; p2 += v2 * v2;
        }

    const size_t F = (size_t)BB * GG * NN * NN;
#pragma unroll
    for (int a = 0; a < 4; a++) {
        size_t off = (((size_t)b * GG + g) * NN + i0 + ti * 4 + a) * NN + j0 + tj * 4;
        union { __half2 h2[2]; uint2 u; } pk;
        pk.h2[0] = __floats2half2_rn(aqk[a][0], aqk[a][1]);
        pk.h2[1] = __floats2half2_rn(aqk[a][2], aqk[a][3]);
        *(uint2*)(d_stkh + off) = pk.u;
        pk.h2[0] = __floats2half2_rn(aqr[a][0], aqr[a][1]);
        pk.h2[1] = __floats2half2_rn(aqr[a][2], aqr[a][3]);
        *(uint2*)(d_stkh + F + off) = pk.u;
        pk.h2[0] = __floats2half2_rn(akr[a][0], akr[a][1]);
        pk.h2[1] = __floats2half2_rn(akr[a][2], akr[a][3]);
        *(uint2*)(d_stkh + 2 * F + off) = pk.u;
    }

#pragma unroll
    for (int off = 16; off; off >>= 1) {
        s0 += __shfl_xor_sync(0xffffffffu, s0, off);
        p0 += __shfl_xor_sync(0xffffffffu, p0, off);
        s1 += __shfl_xor_sync(0xffffffffu, s1, off);
        p1 += __shfl_xor_sync(0xffffffffu, p1, off);
        s2 += __shfl_xor_sync(0xffffffffu, s2, off);
        p2 += __shfl_xor_sync(0xffffffffu, p2, off);
    }
    int warp = tid >> 5, lane = tid & 31;
    if (lane == 0) {
        red[warp][0] = s0; red[warp][1] = p0;
        red[warp][2] = s1; red[warp][3] = p1;
        red[warp][4] = s2; red[warp][5] = p2;
    }
    __syncthreads();
    if (tid < 6) {
        float t = 0.f;
#pragma unroll
        for (int w = 0; w < 8; w++) t += red[w][tid];
        int s = tid >> 1, which = tid & 1;
        atomicAdd(&d_simstats[(s * 8 + g) * 2 + which], t);
    }
}

// ---------------- K5: sim BN + softmax + sv + sve ----------------
// grid (8 itiles of 32, G, B), 256 threads; vectorized load phase,
// mainloop on 128 threads with (c, c+32) x 8 il register tile.
#define AT_PP 260
#define AT_PV 260
#define AT_PR 324
__global__ __launch_bounds__(256, 1)
void k_attn(const float* __restrict__ gsim, const float* __restrict__ bsim) {
    extern __shared__ float sm[];
    float* p     = sm;                      // 32 x AT_PP
    float* vbs   = p + 32 * AT_PP;          // 64 x AT_PV
    float* relV  = vbs + 64 * AT_PV;        // 64 x AT_PR
    float* stage = relV + 64 * AT_PR;       // 64 x 33
    int it = blockIdx.x, g = blockIdx.y, b = blockIdx.z;
    int i0 = it * 32;
    int tid = threadIdx.x;

    const float NELI = 1.0f / (64.0f * 256.0f * 256.0f);
    float aS[3], cS[3];
#pragma unroll
    for (int s = 0; s < 3; s++) {
        int ch = s * 8 + g;
        float m = d_simstats[ch * 2] * NELI;
        float var = d_simstats[ch * 2 + 1] * NELI - m * m;
        float a = gsim[ch] * rsqrtf(var + EPSV);
        aS[s] = a; cS[s] = bsim[ch] - m * a;
    }
    float cSum = cS[0] + cS[1] + cS[2];

    const size_t F = (size_t)BB * GG * NN * NN;
    // --- p load: vectorized, thread -> (il, 4 j) ---
    {
        size_t baseL = (((size_t)b * GG + g) * NN + i0) * NN;
        for (int idx = tid; idx < 2048; idx += 256) {
            int il = idx >> 6, q4 = (idx & 63) * 4;
            size_t off = baseL + (size_t)il * NN + q4;
            union { uint2 u; __half2 h[2]; } v0, v1, v2;
            v0.u = *(const uint2*)(d_stkh + off);
            v1.u = *(const uint2*)(d_stkh + F + off);
            v2.u = *(const uint2*)(d_stkh + 2 * F + off);
            float4 L;
            float2 a0 = __half22float2(v0.h[0]), a1 = __half22float2(v1.h[0]), a2 = __half22float2(v2.h[0]);
            float2 b0 = __half22float2(v0.h[1]), b1 = __half22float2(v1.h[1]), b2 = __half22float2(v2.h[1]);
            L.x = aS[0] * a0.x + aS[1] * a1.x + aS[2] * a2.x + cSum;
            L.y = aS[0] * a0.y + aS[1] * a1.y + aS[2] * a2.y + cSum;
            L.z = aS[0] * b0.x + aS[1] * b1.x + aS[2] * b2.x + cSum;
            L.w = aS[0] * b0.y + aS[1] * b1.y + aS[2] * b2.y + cSum;
            *(float4*)&p[il * AT_PP + q4] = L;
        }
    }
    // --- vbs load: vectorized, thread -> (c, 4 j) ---
    for (int idx = tid; idx < 4096; idx += 256) {
        int c = idx >> 6, q4 = (idx & 63) * 4;
        int o = g * 128 + 2 * HC + c;
        float4 v = *(const float4*)(d_qkv + ((size_t)b * OO + o) * NN + q4);
        float a = d_bnA[o], cc = d_bnC[o];
        v.x = a * v.x + cc; v.y = a * v.y + cc; v.z = a * v.z + cc; v.w = a * v.w + cc;
        *(float4*)&vbs[c * AT_PV + q4] = v;
    }
    // --- relV load: vectorized from padded d_relp ---
    for (int idx = tid; idx < 64 * 72; idx += 256) {
        int c = idx / 72, q4 = (idx - c * 72) * 4;
        float4 v = *(const float4*)(d_relp + c * 512 + i0 + q4);
        *(float4*)&relV[c * AT_PR + q4] = v;
    }
    __syncthreads();

    // softmax over j, one warp per row group
    int warp = tid >> 5, lane = tid & 31;
    for (int r = warp; r < 32; r += 8) {
        float* row = p + r * AT_PP;
        float v[8];
        float mx = -1e30f;
#pragma unroll
        for (int k = 0; k < 8; k++) { v[k] = row[lane + 32 * k]; mx = fmaxf(mx, v[k]); }
#pragma unroll
        for (int off = 16; off; off >>= 1) mx = fmaxf(mx, __shfl_xor_sync(0xffffffffu, mx, off));
        float sum = 0.f;
#pragma unroll
        for (int k = 0; k < 8; k++) { v[k] = expf(v[k] - mx); sum += v[k]; }
#pragma unroll
        for (int off = 16; off; off >>= 1) sum += __shfl_xor_sync(0xffffffffu, sum, off);
        float inv = 1.0f / sum;
#pragma unroll
        for (int k = 0; k < 8; k++) row[lane + 32 * k] = v[k] * inv;
    }
    __syncthreads();

    // sv / sve mainloop: threads 0-127; thread -> (c0=cp, c1=cp+32) x 8 il.
    if (tid < 128) {
        int cp  = tid & 31;
        int il0 = (tid >> 5) * 8;       // 0,8,16,24
        int c0 = cp, c1 = cp + 32;
        float asv0[8], asve0[8], asv1[8], asve1[8];
#pragma unroll
        for (int k = 0; k < 8; k++) { asv0[k] = 0.f; asve0[k] = 0.f; asv1[k] = 0.f; asve1[k] = 0.f; }

#pragma unroll 1
        for (int j0 = 0; j0 < 256; j0 += 4) {
            float4 vb40 = *(const float4*)&vbs[c0 * AT_PV + j0];
            float4 vb41 = *(const float4*)&vbs[c1 * AT_PV + j0];
            int basev = il0 + 252 - j0;
            float4 r00 = *(const float4*)&relV[c0 * AT_PR + basev];
            float4 r01 = *(const float4*)&relV[c0 * AT_PR + basev + 4];
            float4 r02 = *(const float4*)&relV[c0 * AT_PR + basev + 8];
            float4 r10 = *(const float4*)&relV[c1 * AT_PR + basev];
            float4 r11 = *(const float4*)&relV[c1 * AT_PR + basev + 4];
            float4 r12 = *(const float4*)&relV[c1 * AT_PR + basev + 8];
            float rr0[12] = {r00.x, r00.y, r00.z, r00.w, r01.x, r01.y, r01.z, r01.w,
                             r02.x, r02.y, r02.z, r02.w};
            float rr1[12] = {r10.x, r10.y, r10.z, r10.w, r11.x, r11.y, r11.z, r11.w,
                             r12.x, r12.y, r12.z, r12.w};
            float vb0[4] = {vb40.x, vb40.y, vb40.z, vb40.w};
            float vb1[4] = {vb41.x, vb41.y, vb41.z, vb41.w};
#pragma unroll
            for (int k = 0; k < 8; k++) {
                float4 p4 = *(const float4*)&p[(il0 + k) * AT_PP + j0];
                float pv[4] = {p4.x, p4.y, p4.z, p4.w};
#pragma unroll
                for (int e = 0; e < 4; e++) {
                    asv0[k]  += pv[e] * vb0[e];
                    asve0[k] += pv[e] * rr0[3 + k - e];
                    asv1[k]  += pv[e] * vb1[e];
                    asve1[k] += pv[e] * rr1[3 + k - e];
                }
            }
        }

#pragma unroll
        for (int k = 0; k < 8; k++) {
            stage[c0 * 33 + il0 + k] = asv0[k] * F_SV;
            stage[c1 * 33 + il0 + k] = asv1[k] * F_SV;
        }
#pragma unroll
        for (int k = 0; k < 8; k++) { asv0[k] = asve0[k]; asv1[k] = asve1[k]; }
        __syncthreads();
        size_t baseO = (((size_t)b * GG + g) * VC) * NN + i0;
        for (int idx = tid; idx < 2048; idx += 128) {
            int cc = idx >> 5, ii = idx & 31;
            d_sv[baseO + (size_t)cc * NN + ii] = stage[cc * 33 + ii];
        }
        __syncthreads();
#pragma unroll
        for (int k = 0; k < 8; k++) {
            stage[c0 * 33 + il0 + k] = asv0[k] * F_SVE;
            stage[c1 * 33 + il0 + k] = asv1[k] * F_SVE;
        }
        __syncthreads();
        for (int idx = tid; idx < 2048; idx += 128) {
            int cc = idx >> 5, ii = idx & 31;
            d_sve[baseO + (size_t)cc * NN + ii] = stage[cc * 33 + ii];
        }
    } else {
        __syncthreads();
        __syncthreads();
        __syncthreads();
    }
}

// ---------------- K6: out BN stats ----------------
__global__ void k_out_stats(const float* __restrict__ gout, const float* __restrict__ bout) {
    __shared__ float sh[512];
    int ch = blockIdx.x;
    int g = ch >> 7, rem = ch & 127, c = rem >> 1, t = rem & 1;
    int tid = threadIdx.x;
    const float* src = (t ? d_sve : d_sv) + (((size_t)g) * VC + c) * NN + tid;
    float s = 0.f, ss = 0.f;
    for (int b = 0; b < BB; b++) {
        float v = src[(size_t)b * GG * VC * NN];
        s += v; ss += v * v;
    }
    block_reduce2(s, ss, sh);
    if (tid == 0) {
        float m = s / 16384.0f;
        float var = ss / 16384.0f - m * m;
        float a = gout[ch] * rsqrtf(var + EPSV);
        d_outA[ch] = a;
        d_outC[ch] = bout[ch] - m * a;
    }
}

// ---------------- K7: final combine ----------------
__global__ void k_final(float* __restrict__ out) {
    size_t idx = (size_t)blockIdx.x * 256 + threadIdx.x;
    int n = idx & 255;
    int pch = (int)((idx >> 8) & 511);
    int b = (int)(idx >> 17);
    int g = pch >> 6, c = pch & 63;
    size_t si = (((size_t)b * GG + g) * VC + c) * NN + n;
    float sv = d_sv[si], sve = d_sve[si];
    int ch0 = pch * 2, ch1 = ch0 + 1;
    out[idx] = d_outA[ch0] * sv + d_outC[ch0] + d_outA[ch1] * sve + d_outC[ch1];
}

// ---------------- launch ----------------
extern "C" void kernel_launch(void* const* d_in, const int* in_sizes, int n_in,
                              void* d_out, int out_size) {
    const float* x    = (const float*)d_in[0];
    const float* wqkv = (const float*)d_in[1];
    const float* rel  = (const float*)d_in[2];
    const float* gq   = (const float*)d_in[3];
    const float* bq   = (const float*)d_in[4];
    const float* gs   = (const float*)d_in[5];
    const float* bs   = (const float*)d_in[6];
    const float* go   = (const float*)d_in[7];
    const float* bo   = (const float*)d_in[8];
    float* out = (float*)d_out;

    size_t smemK1 = SM_MMA;                                                      // 81920 B
    size_t smemK3 = (size_t)(2 * 32 * SR_PQ + 2 * 32 * SR_PR) * sizeof(float);   // 51200 B
    size_t smemK5 = (size_t)(32 * AT_PP + 64 * AT_PV + 64 * AT_PR + 64 * 33) * sizeof(float); // 191232 B
    cudaFuncSetAttribute(k_qkv_mma, cudaFuncAttributeMaxDynamicSharedMemorySize, (int)smemK1);
    cudaFuncSetAttribute(k_sim_raw, cudaFuncAttributeMaxDynamicSharedMemorySize, (int)smemK3);
    cudaFuncSetAttribute(k_attn,    cudaFuncAttributeMaxDynamicSharedMemorySize, (int)smemK5);

    __nv_bfloat16 *xh, *xl, *wh, *wl;
    cudaGetSymbolAddress((void**)&xh, d_xh);
    cudaGetSymbolAddress((void**)&xl, d_xl);
    cudaGetSymbolAddress((void**)&wh, d_wh);
    cudaGetSymbolAddress((void**)&wl, d_wl);

    k_zero_stats<<<1, 64>>>();
    k_relprep<<<(64 * 511 + 255) / 256, 256>>>(rel);
    {
        int n4x = (BB * NN * CC) / 4;
        k_split<<<n4x / 256, 256>>>((const float4*)x, (uint2*)xh, (uint2*)xl, n4x);
        int n4w = (OO * CC) / 4;
        k_split<<<n4w / 256, 256>>>((const float4*)wqkv, (uint2*)wh, (uint2*)wl, n4w);
    }
    {
        dim3 grid(NN / 128, OO / 128, BB);
        k_qkv_mma<<<grid, 256, smemK1>>>();
    }
    k_qkv_stats<<<OO, 256>>>(gq, bq);
    {
        dim3 grid(16, GG, BB);
        k_sim_raw<<<grid, 256, smemK3>>>(rel);
    }
    {
        dim3 grid(8, GG, BB);
        k_attn<<<grid, 256, smemK5>>>(gs, bs);
    }
    k_out_stats<<<OO, 256>>>(go, bo);
    {
        size_t total = (size_t)BB * 512 * NN;
        k_final<<<(unsigned)(total / 256), 256>>>(out);
    }
}

// round 16
// speedup vs baseline: 1.2480x; 1.2480x over previous
#include <cuda_runtime.h>
#include <cuda_fp16.h>
#include <cuda_bf16.h>
#include <math.h>
#include <stdint.h>

// ---------------- problem constants ----------------
#define BB   64          // batch
#define NN   256         // sequence length (K in reference)
#define CC   512         // input channels
#define OO   1024        // qkv channels (2*OUT_PLANES)
#define GG   8           // groups
#define HC   32          // half group planes (q/k channels per group)
#define VC   64          // v channels per group
#define EPSV 1e-5f
#define F_QR 0.1f
#define F_KR 0.1f
#define F_SVE 0.1f
#define F_SV  1.0f

// ---------------- scratch (static device allocations) ----------------
__device__ float d_qkv[(size_t)BB * OO * NN];                 // 64 MB
__device__ float d_bnA[OO];
__device__ float d_bnC[OO];
__device__ __half d_stkh[(size_t)3 * BB * GG * NN * NN];      // 201 MB (qk,qr,kr raw, fp16)
__device__ float d_simstats[48];                              // 24 ch x (sum,sumsq)
__device__ float d_sv [(size_t)BB * GG * VC * NN];            // 33.5 MB
__device__ float d_sve[(size_t)BB * GG * VC * NN];            // 33.5 MB
__device__ float d_outA[OO];
__device__ float d_outC[OO];
// bf16 hi/lo splits for the tensor-core GEMM
__device__ __nv_bfloat16 d_xh[(size_t)BB * NN * CC];          // 16.8 MB
__device__ __nv_bfloat16 d_xl[(size_t)BB * NN * CC];
__device__ __nv_bfloat16 d_wh[(size_t)OO * CC];               // 1 MB
__device__ __nv_bfloat16 d_wl[(size_t)OO * CC];

// ---------------- small helpers ----------------
__device__ __forceinline__ uint32_t smem_u32(const void* p) {
    uint32_t a;
    asm("{ .reg .u64 t; cvta.to.shared.u64 t, %1; cvt.u32.u64 %0, t; }" : "=r"(a) : "l"(p));
    return a;
}
__device__ __forceinline__ void cpa16(uint32_t s, const __nv_bfloat16* g) {
    asm volatile("cp.async.cg.shared.global [%0], [%1], 16;" :: "r"(s), "l"(g));
}
#define CP_COMMIT() asm volatile("cp.async.commit_group;" ::: "memory")
#define CP_WAIT0()  asm volatile("cp.async.wait_group 0;" ::: "memory")

#define LDM4(R0, R1, R2, R3, ADDR)                                              \
    asm volatile("ldmatrix.sync.aligned.m8n8.x4.shared.b16 {%0,%1,%2,%3}, [%4];" \
                 : "=r"(R0), "=r"(R1), "=r"(R2), "=r"(R3) : "r"(ADDR))

#define MMA_BF16(C, A0, A1, A2, A3, B0, B1)                                     \
    asm volatile("mma.sync.aligned.m16n8k16.row.col.f32.bf16.bf16.f32 "         \
                 "{%0,%1,%2,%3}, {%4,%5,%6,%7}, {%8,%9}, {%0,%1,%2,%3};"        \
                 : "+f"((C)[0]), "+f"((C)[1]), "+f"((C)[2]), "+f"((C)[3])       \
                 : "r"(A0), "r"(A1), "r"(A2), "r"(A3), "r"(B0), "r"(B1))

// ---------------- K0: zero sim stats (must run every replay) ----------------
__global__ void k_zero_stats() {
    int t = threadIdx.x;
    if (t < 48) d_simstats[t] = 0.0f;
}

// ---------------- K-prep: fp32 -> bf16 hi/lo split ----------------
__global__ void k_split(const float4* __restrict__ s, uint2* __restrict__ hi,
                        uint2* __restrict__ lo, int n4) {
    int i = blockIdx.x * 256 + threadIdx.x;
    if (i >= n4) return;
    float4 v = s[i];
    float f[4] = {v.x, v.y, v.z, v.w};
    union { __nv_bfloat16 b[4]; uint2 u; } ph, pl;
#pragma unroll
    for (int e = 0; e < 4; e++) {
        __nv_bfloat16 h = __float2bfloat16(f[e]);
        ph.b[e] = h;
        pl.b[e] = __float2bfloat16(f[e] - __bfloat162float(h));
    }
    hi[i] = ph.u;
    lo[i] = pl.u;
}

// ---------------- K1: qkv GEMM via bf16 mma.sync (hi/lo split, cp.async, ldmatrix) ----------
#define SPB    40                       // smem pitch in bf16 (80 B rows: conflict-free)
#define ABYTES (128 * SPB * 2)          // 10240 B per array
#define OWH    0
#define OWL    ABYTES
#define OXH    (2 * ABYTES)
#define OXL    (3 * ABYTES)
#define BUFB   (4 * ABYTES)             // 40960 B per buffer
#define SM_MMA (2 * BUFB)               // 81920 B

__global__ __launch_bounds__(256, 2)
void k_qkv_mma() {
    extern __shared__ char smc[];
    uint32_t sbase = smem_u32(smc);
    int tid = threadIdx.x;
    int n0 = blockIdx.x * 128, o0 = blockIdx.y * 128, b = blockIdx.z;

    int lrow = tid >> 1;
    int seg  = (tid & 1) * 16;
    const __nv_bfloat16* gwh = d_wh + (size_t)(o0 + lrow) * CC + seg;
    const __nv_bfloat16* gwl = d_wl + (size_t)(o0 + lrow) * CC + seg;
    const __nv_bfloat16* gxh = d_xh + ((size_t)b * NN + n0 + lrow) * CC + seg;
    const __nv_bfloat16* gxl = d_xl + ((size_t)b * NN + n0 + lrow) * CC + seg;
    uint32_t sdst = (uint32_t)(lrow * SPB + seg) * 2;

    int warp = tid >> 5, lane = tid & 31;
    int wo = warp >> 2, wn = warp & 3;
    int t8 = lane >> 3, r8 = lane & 7;
    uint32_t aoff = (uint32_t)(((wo * 64 + (t8 & 1) * 8 + r8) * SPB + (t8 >> 1) * 8) * 2);
    uint32_t boff = (uint32_t)(((wn * 32 + (t8 >> 1) * 8 + r8) * SPB + (t8 & 1) * 8) * 2);

    float acc[4][4][4];
#pragma unroll
    for (int mt = 0; mt < 4; mt++)
#pragma unroll
        for (int nt = 0; nt < 4; nt++)
#pragma unroll
            for (int e = 0; e < 4; e++) acc[mt][nt][e] = 0.0f;

    auto stage = [&](int buf, int c0) {
        uint32_t base = sbase + buf * BUFB + sdst;
        cpa16(base + OWH,      gwh + c0);
        cpa16(base + OWH + 16, gwh + c0 + 8);
        cpa16(base + OWL,      gwl + c0);
        cpa16(base + OWL + 16, gwl + c0 + 8);
        cpa16(base + OXH,      gxh + c0);
        cpa16(base + OXH + 16, gxh + c0 + 8);
        cpa16(base + OXL,      gxl + c0);
        cpa16(base + OXL + 16, gxl + c0 + 8);
        CP_COMMIT();
    };

    stage(0, 0);
    for (int kt = 0; kt < 16; kt++) {
        CP_WAIT0();
        __syncthreads();
        if (kt < 15) stage((kt + 1) & 1, (kt + 1) * 32);
        uint32_t cb = sbase + (uint32_t)(kt & 1) * BUFB;
#pragma unroll
        for (int ks = 0; ks < 2; ks++) {
            uint32_t kb = (uint32_t)ks * 32;
            uint32_t bh[2][4], bl[2][4];
#pragma unroll
            for (int ntp = 0; ntp < 2; ntp++) {
                uint32_t ba = cb + boff + (uint32_t)ntp * (16 * SPB * 2) + kb;
                LDM4(bh[ntp][0], bh[ntp][1], bh[ntp][2], bh[ntp][3], ba + OXH);
                LDM4(bl[ntp][0], bl[ntp][1], bl[ntp][2], bl[ntp][3], ba + OXL);
            }
#pragma unroll
            for (int mt = 0; mt < 4; mt++) {
                uint32_t aa = cb + aoff + (uint32_t)mt * (16 * SPB * 2) + kb;
                uint32_t ah[4], al[4];
                LDM4(ah[0], ah[1], ah[2], ah[3], aa + OWH);
                LDM4(al[0], al[1], al[2], al[3], aa + OWL);
#pragma unroll
                for (int nt = 0; nt < 4; nt++) {
                    int ntp = nt >> 1, h = nt & 1;
                    uint32_t b0h = bh[ntp][h * 2], b1h = bh[ntp][h * 2 + 1];
                    uint32_t b0l = bl[ntp][h * 2], b1l = bl[ntp][h * 2 + 1];
                    MMA_BF16(acc[mt][nt], ah[0], ah[1], ah[2], ah[3], b0h, b1h);
                    MMA_BF16(acc[mt][nt], ah[0], ah[1], ah[2], ah[3], b0l, b1l);
                    MMA_BF16(acc[mt][nt], al[0], al[1], al[2], al[3], b0h, b1h);
                }
            }
        }
    }

    int lr = lane >> 2, lc = lane & 3;
    float* outp = d_qkv + ((size_t)b * OO + o0) * NN + n0;
#pragma unroll
    for (int mt = 0; mt < 4; mt++) {
        int orow = wo * 64 + mt * 16 + lr;
#pragma unroll
        for (int nt = 0; nt < 4; nt++) {
            int ncol = wn * 32 + nt * 8 + lc * 2;
            *(float2*)(outp + (size_t)orow * NN + ncol)       = make_float2(acc[mt][nt][0], acc[mt][nt][1]);
            *(float2*)(outp + (size_t)(orow + 8) * NN + ncol) = make_float2(acc[mt][nt][2], acc[mt][nt][3]);
        }
    }
}

// ---------------- block reduce helper ----------------
__device__ __forceinline__ void block_reduce2(float& s, float& ss, float* sh) {
    int tid = threadIdx.x;
    float* shs = sh;
    float* shq = sh + 256;
    shs[tid] = s; shq[tid] = ss;
    __syncthreads();
    for (int step = 128; step > 0; step >>= 1) {
        if (tid < step) { shs[tid] += shs[tid + step]; shq[tid] += shq[tid + step]; }
        __syncthreads();
    }
    s = shs[0]; ss = shq[0];
}

// ---------------- K2: qkv BN -> per-channel affine ----------------
__global__ void k_qkv_stats(const float* __restrict__ gq, const float* __restrict__ bq) {
    __shared__ float sh[512];
    int o = blockIdx.x;
    int tid = threadIdx.x;
    float s = 0.f, ss = 0.f;
    const float* base = d_qkv + (size_t)o * NN + tid;
    for (int b = 0; b < BB; b++) {
        float v = base[(size_t)b * OO * NN];
        s += v; ss += v * v;
    }
    block_reduce2(s, ss, sh);
    if (tid == 0) {
        float m = s / 16384.0f;
        float var = ss / 16384.0f - m * m;
        float a = gq[o] * rsqrtf(var + EPSV);
        d_bnA[o] = a;
        d_bnC[o] = bq[o] - m * a;
    }
}

// ---------------- K3: raw qk/qr/kr + channel stats (diagonal register-tiled) ----------------
#define SR_PQ 68
#define SR_PR 132
__global__ __launch_bounds__(256, 2)
void k_sim_raw(const float* __restrict__ rel) {
    extern __shared__ float sm[];
    float* qs  = sm;
    float* ks  = qs + 32 * SR_PQ;
    float* rqa = ks + 32 * SR_PQ;
    float* rkb = rqa + 32 * SR_PR;
    __shared__ float red[8][6];

    int bx = blockIdx.x;
    int it = bx >> 2, jt = bx & 3;
    int g = blockIdx.y, b = blockIdx.z;
    int i0 = it * 64, j0 = jt * 64;
    int tid = threadIdx.x;

    int offA = 192 + (i0 - j0);
    int offB = 192 + (j0 - i0);
    for (int idx = tid; idx < 32 * 127; idx += 256) {
        int c = idx / 127, t = idx - c * 127;
        rqa[c * SR_PR + t] = rel[(size_t)c * 511 + offA + t];
        rkb[c * SR_PR + t] = rel[(size_t)(32 + c) * 511 + offB + t];
    }
    for (int idx = tid; idx < 2048; idx += 256) {
        int c = idx >> 6, v = idx & 63;
        int oq = g * 128 + c;
        int ok = g * 128 + HC + c;
        qs[c * SR_PQ + v] = d_bnA[oq] * d_qkv[((size_t)b * OO + oq) * NN + i0 + v] + d_bnC[oq];
        ks[c * SR_PQ + v] = d_bnA[ok] * d_qkv[((size_t)b * OO + ok) * NN + j0 + v] + d_bnC[ok];
    }
    __syncthreads();

    int ti = tid >> 4, tj = tid & 15;
    float aqk[4][4], aqr[4][4], akr[4][4];
#pragma unroll
    for (int a = 0; a < 4; a++)
#pragma unroll
        for (int e = 0; e < 4; e++) { aqk[a][e] = 0.f; aqr[a][e] = 0.f; akr[a][e] = 0.f; }

    int baseA = 4 * (ti - tj) + 60;
    int baseB = 4 * (tj - ti) + 60;

#pragma unroll 2
    for (int c = 0; c < 32; c++) {
        float4 q4  = *(const float4*)&qs[c * SR_PQ + ti * 4];
        float4 k4  = *(const float4*)&ks[c * SR_PQ + tj * 4];
        float4 ra0 = *(const float4*)&rqa[c * SR_PR + baseA];
        float4 ra1 = *(const float4*)&rqa[c * SR_PR + baseA + 4];
        float4 rb0 = *(const float4*)&rkb[c * SR_PR + baseB];
        float4 rb1 = *(const float4*)&rkb[c * SR_PR + baseB + 4];
        float qv[4] = {q4.x, q4.y, q4.z, q4.w};
        float kv[4] = {k4.x, k4.y, k4.z, k4.w};
        float ra[8] = {ra0.x, ra0.y, ra0.z, ra0.w, ra1.x, ra1.y, ra1.z, ra1.w};
        float rb[8] = {rb0.x, rb0.y, rb0.z, rb0.w, rb1.x, rb1.y, rb1.z, rb1.w};
#pragma unroll
        for (int a = 0; a < 4; a++)
#pragma unroll
            for (int e = 0; e < 4; e++) {
                aqk[a][e] += qv[a] * kv[e];
                aqr[a][e] += qv[a] * ra[3 + a - e];
                akr[a][e] += kv[e] * rb[3 + e - a];
            }
    }

    float s0 = 0, p0 = 0, s1 = 0, p1 = 0, s2 = 0, p2 = 0;
#pragma unroll
    for (int a = 0; a < 4; a++)
#pragma unroll
        for (int e = 0; e < 4; e++) {
            aqr[a][e] *= F_QR;
            akr[a][e] *= F_KR;
            float v0 = aqk[a][e], v1 = aqr[a][e], v2 = akr[a][e];
            s0 += v0; p0 += v0 * v0;
            s1 += v1; p1 += v1 * v1;
            s2 += v2; p2 += v2 * v2;
        }

    const size_t F = (size_t)BB * GG * NN * NN;
#pragma unroll
    for (int a = 0; a < 4; a++) {
        size_t off = (((size_t)b * GG + g) * NN + i0 + ti * 4 + a) * NN + j0 + tj * 4;
        union { __half2 h2[2]; uint2 u; } pk;
        pk.h2[0] = __floats2half2_rn(aqk[a][0], aqk[a][1]);
        pk.h2[1] = __floats2half2_rn(aqk[a][2], aqk[a][3]);
        *(uint2*)(d_stkh + off) = pk.u;
        pk.h2[0] = __floats2half2_rn(aqr[a][0], aqr[a][1]);
        pk.h2[1] = __floats2half2_rn(aqr[a][2], aqr[a][3]);
        *(uint2*)(d_stkh + F + off) = pk.u;
        pk.h2[0] = __floats2half2_rn(akr[a][0], akr[a][1]);
        pk.h2[1] = __floats2half2_rn(akr[a][2], akr[a][3]);
        *(uint2*)(d_stkh + 2 * F + off) = pk.u;
    }

#pragma unroll
    for (int off = 16; off; off >>= 1) {
        s0 += __shfl_xor_sync(0xffffffffu, s0, off);
        p0 += __shfl_xor_sync(0xffffffffu, p0, off);
        s1 += __shfl_xor_sync(0xffffffffu, s1, off);
        p1 += __shfl_xor_sync(0xffffffffu, p1, off);
        s2 += __shfl_xor_sync(0xffffffffu, s2, off);
        p2 += __shfl_xor_sync(0xffffffffu, p2, off);
    }
    int warp = tid >> 5, lane = tid & 31;
    if (lane == 0) {
        red[warp][0] = s0; red[warp][1] = p0;
        red[warp][2] = s1; red[warp][3] = p1;
        red[warp][4] = s2; red[warp][5] = p2;
    }
    __syncthreads();
    if (tid < 6) {
        float t = 0.f;
#pragma unroll
        for (int w = 0; w < 8; w++) t += red[w][tid];
        int s = tid >> 1, which = tid & 1;
        atomicAdd(&d_simstats[(s * 8 + g) * 2 + which], t);
    }
}

// ---------------- K5: sim BN + softmax + sv + sve ----------------
// grid (8 itiles of 32, G, B), 256 threads (R14 structure).
// mainloop: 128 threads, (c, c+32) x 8 il, j0 unrolled x2 for ILP.
#define AT_PP 260
#define AT_PV 260
#define AT_PR 324
__global__ __launch_bounds__(256, 1)
void k_attn(const float* __restrict__ rel,
            const float* __restrict__ gsim, const float* __restrict__ bsim) {
    extern __shared__ float sm[];
    float* p     = sm;                      // 32 x AT_PP
    float* vbs   = p + 32 * AT_PP;          // 64 x AT_PV
    float* relV  = vbs + 64 * AT_PV;        // 64 x AT_PR
    float* stage = relV + 64 * AT_PR;       // 64 x 33
    int it = blockIdx.x, g = blockIdx.y, b = blockIdx.z;
    int i0 = it * 32;
    int tid = threadIdx.x;

    const float NELI = 1.0f / (64.0f * 256.0f * 256.0f);
    float aS[3], cS[3];
#pragma unroll
    for (int s = 0; s < 3; s++) {
        int ch = s * 8 + g;
        float m = d_simstats[ch * 2] * NELI;
        float var = d_simstats[ch * 2 + 1] * NELI - m * m;
        float a = gsim[ch] * rsqrtf(var + EPSV);
        aS[s] = a; cS[s] = bsim[ch] - m * a;
    }

    const size_t F = (size_t)BB * GG * NN * NN;
    size_t baseL = (((size_t)b * GG + g) * NN + i0) * NN + tid;
    for (int il = 0; il < 32; il++) {
        size_t off = baseL + (size_t)il * NN;
        float L = aS[0] * __half2float(d_stkh[off]) + cS[0]
                + aS[1] * __half2float(d_stkh[F + off]) + cS[1]
                + aS[2] * __half2float(d_stkh[2 * F + off]) + cS[2];
        p[il * AT_PP + tid] = L;
    }
    for (int c = 0; c < VC; c++) {
        int o = g * 128 + 2 * HC + c;
        vbs[c * AT_PV + tid] = d_bnA[o] * d_qkv[((size_t)b * OO + o) * NN + tid] + d_bnC[o];
    }
    for (int idx = tid; idx < 64 * 287; idx += 256) {
        int c = idx / 287, d = idx - c * 287;
        relV[c * AT_PR + d] = rel[(size_t)(64 + c) * 511 + i0 + d];
    }
    __syncthreads();

    // softmax over j, one warp per row group
    int warp = tid >> 5, lane = tid & 31;
    for (int r = warp; r < 32; r += 8) {
        float* row = p + r * AT_PP;
        float v[8];
        float mx = -1e30f;
#pragma unroll
        for (int k = 0; k < 8; k++) { v[k] = row[lane + 32 * k]; mx = fmaxf(mx, v[k]); }
#pragma unroll
        for (int off = 16; off; off >>= 1) mx = fmaxf(mx, __shfl_xor_sync(0xffffffffu, mx, off));
        float sum = 0.f;
#pragma unroll
        for (int k = 0; k < 8; k++) { v[k] = expf(v[k] - mx); sum += v[k]; }
#pragma unroll
        for (int off = 16; off; off >>= 1) sum += __shfl_xor_sync(0xffffffffu, sum, off);
        float inv = 1.0f / sum;
#pragma unroll
        for (int k = 0; k < 8; k++) row[lane + 32 * k] = v[k] * inv;
    }
    __syncthreads();

    // sv / sve mainloop: threads 0-127; thread -> (c0=cp, c1=cp+32) x 8 il.
    int cp  = tid & 31;
    int il0 = (tid >> 5) * 8;       // meaningful for tid<128
    int c0 = cp, c1 = cp + 32;
    float asv0[8], asve0[8], asv1[8], asve1[8];
#pragma unroll
    for (int k = 0; k < 8; k++) { asv0[k] = 0.f; asve0[k] = 0.f; asv1[k] = 0.f; asve1[k] = 0.f; }

    if (tid < 128) {
#pragma unroll 2
        for (int j0 = 0; j0 < 256; j0 += 4) {
            float4 vb40 = *(const float4*)&vbs[c0 * AT_PV + j0];
            float4 vb41 = *(const float4*)&vbs[c1 * AT_PV + j0];
            int basev = il0 + 252 - j0;
            float4 r00 = *(const float4*)&relV[c0 * AT_PR + basev];
            float4 r01 = *(const float4*)&relV[c0 * AT_PR + basev + 4];
            float4 r02 = *(const float4*)&relV[c0 * AT_PR + basev + 8];
            float4 r10 = *(const float4*)&relV[c1 * AT_PR + basev];
            float4 r11 = *(const float4*)&relV[c1 * AT_PR + basev + 4];
            float4 r12 = *(const float4*)&relV[c1 * AT_PR + basev + 8];
            float rr0[12] = {r00.x, r00.y, r00.z, r00.w, r01.x, r01.y, r01.z, r01.w,
                             r02.x, r02.y, r02.z, r02.w};
            float rr1[12] = {r10.x, r10.y, r10.z, r10.w, r11.x, r11.y, r11.z, r11.w,
                             r12.x, r12.y, r12.z, r12.w};
            float vb0[4] = {vb40.x, vb40.y, vb40.z, vb40.w};
            float vb1[4] = {vb41.x, vb41.y, vb41.z, vb41.w};
#pragma unroll
            for (int k = 0; k < 8; k++) {
                float4 p4 = *(const float4*)&p[(il0 + k) * AT_PP + j0];
                float pv[4] = {p4.x, p4.y, p4.z, p4.w};
#pragma unroll
                for (int e = 0; e < 4; e++) {
                    asv0[k]  += pv[e] * vb0[e];
                    asve0[k] += pv[e] * rr0[3 + k - e];
                    asv1[k]  += pv[e] * vb1[e];
                    asve1[k] += pv[e] * rr1[3 + k - e];
                }
            }
        }
        // stage is a distinct smem region; no barrier needed before writing it
#pragma unroll
        for (int k = 0; k < 8; k++) {
            stage[c0 * 33 + il0 + k] = asv0[k] * F_SV;
            stage[c1 * 33 + il0 + k] = asv1[k] * F_SV;
        }
    }
    __syncthreads();
    size_t baseO = (((size_t)b * GG + g) * VC) * NN + i0;
    for (int idx = tid; idx < 2048; idx += 256) {
        int cc = idx >> 5, ii = idx & 31;
        d_sv[baseO + (size_t)cc * NN + ii] = stage[cc * 33 + ii];
    }
    __syncthreads();
    if (tid < 128) {
#pragma unroll
        for (int k = 0; k < 8; k++) {
            stage[c0 * 33 + il0 + k] = asve0[k] * F_SVE;
            stage[c1 * 33 + il0 + k] = asve1[k] * F_SVE;
        }
    }
    __syncthreads();
    for (int idx = tid; idx < 2048; idx += 256) {
        int cc = idx >> 5, ii = idx & 31;
        d_sve[baseO + (size_t)cc * NN + ii] = stage[cc * 33 + ii];
    }
}

// ---------------- K6: out BN stats ----------------
__global__ void k_out_stats(const float* __restrict__ gout, const float* __restrict__ bout) {
    __shared__ float sh[512];
    int ch = blockIdx.x;
    int g = ch >> 7, rem = ch & 127, c = rem >> 1, t = rem & 1;
    int tid = threadIdx.x;
    const float* src = (t ? d_sve : d_sv) + (((size_t)g) * VC + c) * NN + tid;
    float s = 0.f, ss = 0.f;
    for (int b = 0; b < BB; b++) {
        float v = src[(size_t)b * GG * VC * NN];
        s += v; ss += v * v;
    }
    block_reduce2(s, ss, sh);
    if (tid == 0) {
        float m = s / 16384.0f;
        float var = ss / 16384.0f - m * m;
        float a = gout[ch] * rsqrtf(var + EPSV);
        d_outA[ch] = a;
        d_outC[ch] = bout[ch] - m * a;
    }
}

// ---------------- K7: final combine ----------------
__global__ void k_final(float* __restrict__ out) {
    size_t idx = (size_t)blockIdx.x * 256 + threadIdx.x;
    int n = idx & 255;
    int pch = (int)((idx >> 8) & 511);
    int b = (int)(idx >> 17);
    int g = pch >> 6, c = pch & 63;
    size_t si = (((size_t)b * GG + g) * VC + c) * NN + n;
    float sv = d_sv[si], sve = d_sve[si];
    int ch0 = pch * 2, ch1 = ch0 + 1;
    out[idx] = d_outA[ch0] * sv + d_outC[ch0] + d_outA[ch1] * sve + d_outC[ch1];
}

// ---------------- launch ----------------
extern "C" void kernel_launch(void* const* d_in, const int* in_sizes, int n_in,
                              void* d_out, int out_size) {
    const float* x    = (const float*)d_in[0];
    const float* wqkv = (const float*)d_in[1];
    const float* rel  = (const float*)d_in[2];
    const float* gq   = (const float*)d_in[3];
    const float* bq   = (const float*)d_in[4];
    const float* gs   = (const float*)d_in[5];
    const float* bs   = (const float*)d_in[6];
    const float* go   = (const float*)d_in[7];
    const float* bo   = (const float*)d_in[8];
    float* out = (float*)d_out;

    size_t smemK1 = SM_MMA;                                                      // 81920 B
    size_t smemK3 = (size_t)(2 * 32 * SR_PQ + 2 * 32 * SR_PR) * sizeof(float);   // 51200 B
    size_t smemK5 = (size_t)(32 * AT_PP + 64 * AT_PV + 64 * AT_PR + 64 * 33) * sizeof(float); // 191232 B
    cudaFuncSetAttribute(k_qkv_mma, cudaFuncAttributeMaxDynamicSharedMemorySize, (int)smemK1);
    cudaFuncSetAttribute(k_sim_raw, cudaFuncAttributeMaxDynamicSharedMemorySize, (int)smemK3);
    cudaFuncSetAttribute(k_attn,    cudaFuncAttributeMaxDynamicSharedMemorySize, (int)smemK5);

    __nv_bfloat16 *xh, *xl, *wh, *wl;
    cudaGetSymbolAddress((void**)&xh, d_xh);
    cudaGetSymbolAddress((void**)&xl, d_xl);
    cudaGetSymbolAddress((void**)&wh, d_wh);
    cudaGetSymbolAddress((void**)&wl, d_wl);

    k_zero_stats<<<1, 64>>>();
    {
        int n4x = (BB * NN * CC) / 4;
        k_split<<<n4x / 256, 256>>>((const float4*)x, (uint2*)xh, (uint2*)xl, n4x);
        int n4w = (OO * CC) / 4;
        k_split<<<n4w / 256, 256>>>((const float4*)wqkv, (uint2*)wh, (uint2*)wl, n4w);
    }
    {
        dim3 grid(NN / 128, OO / 128, BB);
        k_qkv_mma<<<grid, 256, smemK1>>>();
    }
    k_qkv_stats<<<OO, 256>>>(gq, bq);
    {
        dim3 grid(16, GG, BB);
        k_sim_raw<<<grid, 256, smemK3>>>(rel);
    }
    {
        dim3 grid(8, GG, BB);
        k_attn<<<grid, 256, smemK5>>>(rel, gs, bs);
    }
    k_out_stats<<<OO, 256>>>(go, bo);
    {
        size_t total = (size_t)BB * 512 * NN;
        k_final<<<(unsigned)(total / 256), 256>>>(out);
    }
}